// round 2
// baseline (speedup 1.0000x reference)
#include <cuda_runtime.h>
#include <cstdint>

// EConv: out[dst] += x[src] * edge_attr[e]  over 1M edges, d=64
// d_in[0]: x          float32 [100000*64]
// d_in[1]: edge_index delivered as int32 [2*1000000]  (row 0 = dst, row 1 = src)
// d_in[2]: edge_attr  float32 [1000000*64]
// d_out:   float32 [100000*64]

#define D 64
#define D4 (D / 4)   // 16 float4 chunks per row

__global__ void zero_kernel(float4* out, int n4) {
    int i = blockIdx.x * blockDim.x + threadIdx.x;
    if (i < n4) out[i] = make_float4(0.f, 0.f, 0.f, 0.f);
}

__global__ __launch_bounds__(256) void econv_kernel(
    const float4* __restrict__ x,          // [N, D/4]
    const int* __restrict__ dst_idx,       // [E]
    const int* __restrict__ src_idx,       // [E]
    const float4* __restrict__ edge_attr,  // [E, D/4]
    float* __restrict__ out,               // [N, D]
    int total)                             // E * D4
{
    int tid = blockIdx.x * blockDim.x + threadIdx.x;
    if (tid >= total) return;

    int e = tid >> 4;        // edge id
    int c = tid & 15;        // float4 chunk within the 64-wide row

    int src = __ldg(&src_idx[e]);
    int dst = __ldg(&dst_idx[e]);

    float4 xv = __ldg(&x[(size_t)src * D4 + c]);
    float4 av = __ldg(&edge_attr[(size_t)e * D4 + c]);

    float4 m;
    m.x = xv.x * av.x;
    m.y = xv.y * av.y;
    m.z = xv.z * av.z;
    m.w = xv.w * av.w;

    float* p = out + (size_t)dst * D + c * 4;
    asm volatile(
        "red.global.add.v4.f32 [%0], {%1, %2, %3, %4};"
        :: "l"(p), "f"(m.x), "f"(m.y), "f"(m.z), "f"(m.w)
        : "memory");
}

extern "C" void kernel_launch(void* const* d_in, const int* in_sizes, int n_in,
                              void* d_out, int out_size) {
    const float4* x = (const float4*)d_in[0];
    const int* edge_index = (const int*)d_in[1];
    const float4* edge_attr = (const float4*)d_in[2];
    float* out = (float*)d_out;

    int E = in_sizes[1] / 2;                 // 1,000,000
    const int* dst_idx = edge_index;         // row 0
    const int* src_idx = edge_index + E;     // row 1

    // Zero the output (harness poisons it)
    int n4 = out_size / 4;
    zero_kernel<<<(n4 + 255) / 256, 256>>>((float4*)d_out, n4);

    int total = E * D4;                      // 16M threads
    econv_kernel<<<(total + 255) / 256, 256>>>(
        x, dst_idx, src_idx, edge_attr, out, total);
}

// round 3
// speedup vs baseline: 1.3411x; 1.3411x over previous
#include <cuda_runtime.h>
#include <cstdint>

// EConv: out[dst] += x[src] * edge_attr[e]  over 1M edges, d=64
// d_in[0]: x          float32 [100000*64]
// d_in[1]: edge_index delivered as int32 [2*1000000]  (row 0 = dst, row 1 = src)
// d_in[2]: edge_attr  float32 [1000000*64]
// d_out:   float32 [100000*64]

#define D 64
#define D4 (D / 4)   // 16 float4 chunks per row
#define EPT 4        // edges per thread

__global__ void zero_kernel(float4* out, int n4) {
    int i = blockIdx.x * blockDim.x + threadIdx.x;
    if (i < n4) out[i] = make_float4(0.f, 0.f, 0.f, 0.f);
}

__global__ __launch_bounds__(256) void econv_kernel(
    const float4* __restrict__ x,          // [N, D/4]  (L2-resident, cached)
    const int* __restrict__ dst_idx,       // [E]       (streaming)
    const int* __restrict__ src_idx,       // [E]       (streaming)
    const float4* __restrict__ edge_attr,  // [E, D/4]  (streaming)
    float* __restrict__ out,               // [N, D]
    int E)
{
    int t = blockIdx.x * blockDim.x + threadIdx.x;
    int g = t >> 4;          // edge-group id
    int c = t & 15;          // float4 chunk within the 64-wide row
    int e0 = g * EPT;
    if (e0 >= E) return;

    // Front-batch all index loads (streaming: evict-first)
    int src[EPT], dst[EPT];
#pragma unroll
    for (int i = 0; i < EPT; i++) {
        src[i] = __ldcs(&src_idx[e0 + i]);
        dst[i] = __ldcs(&dst_idx[e0 + i]);
    }

    // Front-batch gathers (keep x cached in L2) and attr streams (evict-first)
    float4 xv[EPT], av[EPT];
#pragma unroll
    for (int i = 0; i < EPT; i++) {
        xv[i] = __ldg(&x[(size_t)src[i] * D4 + c]);
        av[i] = __ldcs(&edge_attr[(size_t)(e0 + i) * D4 + c]);
    }

#pragma unroll
    for (int i = 0; i < EPT; i++) {
        float4 m;
        m.x = xv[i].x * av[i].x;
        m.y = xv[i].y * av[i].y;
        m.z = xv[i].z * av[i].z;
        m.w = xv[i].w * av[i].w;
        float* p = out + (size_t)dst[i] * D + c * 4;
        asm volatile(
            "red.global.add.v4.f32 [%0], {%1, %2, %3, %4};"
            :: "l"(p), "f"(m.x), "f"(m.y), "f"(m.z), "f"(m.w)
            : "memory");
    }
}

extern "C" void kernel_launch(void* const* d_in, const int* in_sizes, int n_in,
                              void* d_out, int out_size) {
    const float4* x = (const float4*)d_in[0];
    const int* edge_index = (const int*)d_in[1];
    const float4* edge_attr = (const float4*)d_in[2];

    int E = in_sizes[1] / 2;                 // 1,000,000
    const int* dst_idx = edge_index;         // row 0
    const int* src_idx = edge_index + E;     // row 1

    // Zero the output (harness poisons it)
    int n4 = out_size / 4;
    zero_kernel<<<(n4 + 255) / 256, 256>>>((float4*)d_out, n4);

    // E/EPT edge groups * 16 chunk-threads
    long long total = (long long)(E / EPT) * 16;  // 4M threads (E divisible by 4)
    int blocks = (int)((total + 255) / 256);
    econv_kernel<<<blocks, 256>>>(
        x, dst_idx, src_idx, edge_attr, (float*)d_out, E);
}